// round 7
// baseline (speedup 1.0000x reference)
#include <cuda_runtime.h>
#include <cuda_bf16.h>

#define NN 32768
#define BB 4
#define WW 512
#define FF 127
#define NFT (BB*FF)
#define TILE 4096
#define NEAR_LO 1792
#define NEAR_SPAN 4096
#define FCH 16            // frames per far-chunk
#define NCH 8             // far chunks

// ---- device scratch ----
__device__ unsigned long long d_amax[NFT];
__device__ float d_Pc[NCH * BB * NN];      // far partials; near adds into chunk 0
__device__ float d_ftab[NFT * 8];          // per frame: {a_bits, r, M0, M1, M2, M3, -, -}
__device__ double d_acc;

__device__ __forceinline__ float hamm(int j) {
    return 0.54f - 0.46f * cospif((float)j * (1.0f / 256.0f));
}

// order-preserving pack; ties -> smaller k wins (matches jnp.argmax)
__device__ __forceinline__ unsigned long long packkey(float v, unsigned k) {
    unsigned u = __float_as_uint(v);
    u = (u & 0x80000000u) ? ~u : (u | 0x80000000u);
    return ((unsigned long long)u << 32) | (0xFFFFFFFFu - k);
}

__global__ void k_init() {
    int i = blockIdx.x * blockDim.x + threadIdx.x;
    if (i < NFT) d_amax[i] = 0ull;
    if (i == NFT) d_acc = 0.0;
}

// Register-sliding-window 512-tap conv: 16 outputs/thread, 8 taps/iter.
// FULLY UNROLLED: no loop back-edge -> rotation copies vanish via renaming,
// all LDS use immediate offsets.
// csh[i] = x[tile0 - 512 + i]; csh valid for i in [-16, 16*nthr + 512).
__device__ __forceinline__ void conv16(const float* __restrict__ csh,
                                       const float* __restrict__ wsh,
                                       int tid, float* __restrict__ acc) {
    float X[24];   // X[i] = csh[16*tid + 504 - j0 + i]
    const float* base = csh + 16 * tid + 504;
#pragma unroll
    for (int i = 0; i < 6; i++) {
        float4 v = *(const float4*)(base + 4 * i);
        X[4*i+0]=v.x; X[4*i+1]=v.y; X[4*i+2]=v.z; X[4*i+3]=v.w;
    }
#pragma unroll 64
    for (int j0 = 0; j0 < 512; j0 += 8) {
        float4 w0 = *(const float4*)(wsh + j0);
        float4 w1 = *(const float4*)(wsh + j0 + 4);
        float wr[8] = {w0.x,w0.y,w0.z,w0.w,w1.x,w1.y,w1.z,w1.w};
#pragma unroll
        for (int c = 0; c < 8; c++)
#pragma unroll
            for (int t = 0; t < 16; t++)
                acc[t] = fmaf(wr[c], X[8 + t - c], acc[t]);
        // slide window by 8: new X[i] = old X[i-8] for i>=8; X[0..7] fresh
#pragma unroll
        for (int i = 23; i >= 8; i--) X[i] = X[i - 8];
        float4 n0 = *(const float4*)(base - j0 - 8);
        float4 n1 = *(const float4*)(base - j0 - 4);
        X[0]=n0.x; X[1]=n0.y; X[2]=n0.z; X[3]=n0.w;
        X[4]=n1.x; X[5]=n1.y; X[6]=n1.z; X[7]=n1.w;
    }
}

// ---- conv1: fm[b,f,k] = sum_j w[j]*t[k-j]; block argmax -> atomicMax ----
__global__ __launch_bounds__(256, 2) void k_conv1(const float* __restrict__ recon,
                                                  const float* __restrict__ target) {
    __shared__ __align__(16) float raw[4640];
    __shared__ __align__(16) float wsh[512];
    __shared__ unsigned long long rsh[256];
    float* csh = raw + 16;
    const int tid = threadIdx.x;
    const int tile0 = blockIdx.x * TILE;
    const int f = blockIdx.y, b = blockIdx.z;
    const float* tb = target + b * NN;
    const float* rb = recon + b * NN + f * 256;

    for (int j = tid; j < 512; j += 256) wsh[j] = hamm(j) * rb[j];
    for (int i = tid; i < 4624; i += 256) {
        int gi = tile0 - 528 + i;
        raw[i] = (gi >= 0 && gi < NN) ? tb[gi] : 0.0f;
    }
    __syncthreads();

    float acc[16];
#pragma unroll
    for (int t = 0; t < 16; t++) acc[t] = 0.0f;
    conv16(csh, wsh, tid, acc);

    unsigned kb = (unsigned)(tile0 + 16 * tid);
    unsigned long long key = packkey(acc[0], kb);
#pragma unroll
    for (int t = 1; t < 16; t++) {
        unsigned long long kt = packkey(acc[t], kb + t);
        if (kt > key) key = kt;
    }
    rsh[tid] = key;
    __syncthreads();
    for (int s = 128; s > 0; s >>= 1) {
        if (tid < s) { if (rsh[tid + s] > rsh[tid]) rsh[tid] = rsh[tid + s]; }
        __syncthreads();
    }
    if (tid == 0) atomicMax(&d_amax[b * FF + f], rsh[0]);
}

// ---- per-frame params + moments for the far-field expansion ----
__global__ void k_prep(const float* __restrict__ recon) {
    __shared__ float4 red[128];
    const int bf = blockIdx.x;
    const int b = bf / FF, f = bf % FF;
    const int tid = threadIdx.x;
    const unsigned a = 0xFFFFFFFFu - (unsigned)(d_amax[bf] & 0xFFFFFFFFull);
    const bool delta = (a == 0u);
    const float r = (float)a * (1.0f / 32769.0f);
    const float beta = delta ? 1.0f
        : ((a & 1u) ? -1.0f : 1.0f) * sinpif(r) * (1.0f / 65536.0f);
    const float* rb = recon + b * NN + f * 256;

    float m0 = 0.f, m1 = 0.f, m2 = 0.f, m3 = 0.f;
#pragma unroll
    for (int q = 0; q < 4; q++) {
        int j = tid * 4 + q;
        float s = (j & 1) ? -1.0f : 1.0f;
        float g = beta * s * hamm(j) * rb[j];
        float tau = (255.5f - (float)j) * (1.0f / 256.0f);
        float t2 = tau * tau;
        m0 += g; m1 += g * tau; m2 += g * t2; m3 += g * t2 * tau;
    }
    red[tid] = make_float4(m0, m1, m2, m3);
    __syncthreads();
    for (int s = 64; s > 0; s >>= 1) {
        if (tid < s) {
            float4 x = red[tid], y = red[tid + s];
            red[tid] = make_float4(x.x+y.x, x.y+y.y, x.z+y.z, x.w+y.w);
        }
        __syncthreads();
    }
    if (tid == 0) {
        float* e = d_ftab + bf * 8;
        float4 m = red[0];
        e[0] = __int_as_float((int)a);
        e[1] = r;
        e[2] = m.x; e[3] = m.y; e[4] = m.z; e[5] = m.w;
    }
}

// ---- far-field: cubic cot-Taylor x moments; frame-chunked for occupancy ----
__global__ __launch_bounds__(256) void k_far() {
    __shared__ float ft[FCH * 8];
    const int tid = threadIdx.x;
    const int chunk = blockIdx.y, b = blockIdx.z;
    const int f0 = chunk * FCH;
    const int nf = (f0 + FCH < FF) ? FCH : (FF - f0);
    for (int i = tid; i < nf * 8; i += 256) ft[i] = d_ftab[(b * FF + f0) * 8 + i];
    __syncthreads();

    const int m0i = blockIdx.x * 1024 + tid * 4;
    float F[4] = {0.f, 0.f, 0.f, 0.f};
    const float G = 0.01227184630f;   // pi/256

    for (int f = 0; f < nf; f++) {
        const float* e = ft + f * 8;
        int a = __float_as_int(e[0]);
        if (a == 0) continue;                      // delta frame: fully in near band
        float r = e[1], M0 = e[2], M1 = e[3], M2 = e[4], M3 = e[5];
        float dbase = (float)(m0i - a) + (r - 255.5f);
        int rel = m0i - (a - NEAR_LO);
#pragma unroll
        for (int k = 0; k < 4; k++) {
            if ((unsigned)(rel + k) < (unsigned)NEAR_SPAN) continue;  // near band: exact
            float u = (dbase + (float)k) * (1.0f / 65536.0f);
            float c0 = __fdividef(cospif(u), sinpif(u));
            float c2 = c0 * c0;
            float q = c2 + 1.0f;
            float t = fmaf(G, fmaf(G, (c2 + 0.33333333f) * M3, -c0 * M2), M1);
            F[k] = fmaf(c0, M0, fmaf(-G * q, t, F[k]));
        }
    }
    // P = (-1)^m * F ; m0i multiple of 4 -> signs + - + -
    float4 outv = make_float4(F[0], -F[1], F[2], -F[3]);
    *(float4*)(d_Pc + ((size_t)(chunk * BB + b)) * NN + m0i) = outv;
}

// ---- near-field: exact 512-tap conv on the 4096-wide band around the pole ----
__global__ __launch_bounds__(256, 2) void k_near(const float* __restrict__ recon) {
    __shared__ __align__(16) float raw[4640];
    __shared__ __align__(16) float wsh[512];
    float* csh = raw + 16;
    const int tid = threadIdx.x;
    const int f = blockIdx.y, b = blockIdx.z;
    const int bf = b * FF + f;
    const unsigned a = 0xFFFFFFFFu - (unsigned)(d_amax[bf] & 0xFFFFFFFFull);
    const int tile0 = (int)a - NEAR_LO;
    const bool delta = (a == 0u);
    const float r = (float)a * (1.0f / 32769.0f);
    const float beta = delta ? 1.0f
        : ((a & 1u) ? -1.0f : 1.0f) * sinpif(r) * (1.0f / 65536.0f);
    const float* rb = recon + b * NN + f * 256;

    for (int j = tid; j < 512; j += 256) {
        float s = (j & 1) ? -1.0f : 1.0f;
        wsh[j] = beta * s * hamm(j) * rb[j];
    }
    for (int i = tid; i < 4624; i += 256) {
        int d = tile0 - 528 + i;
        float v;
        if (delta) {
            v = (d == 0) ? 1.0f : 0.0f;
        } else if (d < -511) {
            v = 0.0f;
        } else {
            float u = ((float)(d - (int)a) + r) * (1.0f / 65536.0f);
            v = __fdividef(cospif(u), sinpif(u));
        }
        raw[i] = v;
    }
    __syncthreads();

    float acc[16];
#pragma unroll
    for (int t = 0; t < 16; t++) acc[t] = 0.0f;
    conv16(csh, wsh, tid, acc);

    const int mb = tile0 + 16 * tid;
    float* Pb = d_Pc + b * NN;        // chunk 0 partial
#pragma unroll
    for (int t = 0; t < 16; t++) {
        int m = mb + t;
        if ((unsigned)m < (unsigned)NN) {
            float val = (m & 1) ? -acc[t] : acc[t];
            atomicAdd(Pb + m, val);
        }
    }
}

// ---- parallel MSE reduction ----
__global__ void k_loss(const float* __restrict__ target) {
    __shared__ double red[256];
    const int tid = threadIdx.x;
    double s = 0.0;
    for (int i = blockIdx.x * 256 + tid; i < BB * NN; i += gridDim.x * 256) {
        int b = i >> 15, m = i & (NN - 1);
        float p = 0.f;
#pragma unroll
        for (int c = 0; c < NCH; c++)
            p += d_Pc[((size_t)(c * BB + b)) * NN + m];
        double dd = (double)p - (double)target[i];
        s += dd * dd;
    }
    red[tid] = s;
    __syncthreads();
    for (int st = 128; st > 0; st >>= 1) {
        if (tid < st) red[tid] += red[tid + st];
        __syncthreads();
    }
    if (tid == 0) atomicAdd(&d_acc, red[0]);
}

__global__ void k_final(float* __restrict__ out) {
    out[0] = (float)(d_acc / (double)(BB * NN));
}

extern "C" void kernel_launch(void* const* d_in, const int* in_sizes, int n_in,
                              void* d_out, int out_size) {
    const float* recon  = (const float*)d_in[0];
    const float* target = (const float*)d_in[1];
    float* out = (float*)d_out;
    (void)in_sizes; (void)n_in; (void)out_size;

    k_init<<<2, 256>>>();
    k_conv1<<<dim3(NN / TILE, FF, BB), 256>>>(recon, target);
    k_prep<<<NFT, 128>>>(recon);
    k_far<<<dim3(NN / 1024, NCH, BB), 256>>>();
    k_near<<<dim3(1, FF, BB), 256>>>(recon);
    k_loss<<<128, 256>>>(target);
    k_final<<<1, 1>>>(out);
}

// round 8
// speedup vs baseline: 1.0889x; 1.0889x over previous
#include <cuda_runtime.h>
#include <cuda_bf16.h>

#define NN 32768
#define BB 4
#define WW 512
#define FF 127
#define NFT (BB*FF)
#define TILE 4096
#define NEAR_LO 1792
#define NEAR_SPAN 4096
#define FCH 16            // frames per far-chunk
#define NCH 8             // far chunks

// ---- device scratch ----
__device__ unsigned long long d_amax[NFT];
__device__ float d_Pc[NCH * BB * NN];      // far partials; near adds into chunk 0
__device__ float d_ftab[NFT * 8];          // per frame: {a_bits, r, M0, M1, M2, M3, -, -}
__device__ double d_acc;

__device__ __forceinline__ float hamm(int j) {
    return 0.54f - 0.46f * cospif((float)j * (1.0f / 256.0f));
}

// order-preserving pack; ties -> smaller k wins (matches jnp.argmax)
__device__ __forceinline__ unsigned long long packkey(float v, unsigned k) {
    unsigned u = __float_as_uint(v);
    u = (u & 0x80000000u) ? ~u : (u | 0x80000000u);
    return ((unsigned long long)u << 32) | (0xFFFFFFFFu - k);
}

__global__ void k_init() {
    int i = blockIdx.x * blockDim.x + threadIdx.x;
    if (i < NFT) d_amax[i] = 0ull;
    if (i == NFT) d_acc = 0.0;
}

// 512-tap conv, 16 outputs/thread, 8 taps/group, NO register window:
// each group reloads its 24-float x span via 6 independent LDS.128
// (no rotation MOVs, no loop-carried register chain).
// csh[i] = x[tile0 - 512 + i]; needs csh valid for i in [0, 16*nthr + 528).
// Output t of thread tid: sum_j w[j] * x[tile0 + 16*tid + t - j].
__device__ __forceinline__ void conv16(const float* __restrict__ csh,
                                       const float* __restrict__ wsh,
                                       int tid, float* __restrict__ acc) {
    const float* base = csh + 16 * tid + 504;
#pragma unroll 8
    for (int j0 = 0; j0 < 512; j0 += 8) {
        float4 w0 = *(const float4*)(wsh + j0);
        float4 w1 = *(const float4*)(wsh + j0 + 4);
        float wr[8] = {w0.x,w0.y,w0.z,w0.w,w1.x,w1.y,w1.z,w1.w};
        float X[24];   // X[q] = csh[16*tid + 504 - j0 + q]
#pragma unroll
        for (int q = 0; q < 6; q++) {
            float4 v = *(const float4*)(base - j0 + 4 * q);
            X[4*q+0]=v.x; X[4*q+1]=v.y; X[4*q+2]=v.z; X[4*q+3]=v.w;
        }
#pragma unroll
        for (int c = 0; c < 8; c++)
#pragma unroll
            for (int t = 0; t < 16; t++)
                acc[t] = fmaf(wr[c], X[8 + t - c], acc[t]);
    }
}

// ---- conv1: fm[b,f,k] = sum_j w[j]*t[k-j]; block argmax -> atomicMax ----
__global__ __launch_bounds__(256, 2) void k_conv1(const float* __restrict__ recon,
                                                  const float* __restrict__ target) {
    __shared__ __align__(16) float raw[4640];
    __shared__ __align__(16) float wsh[512];
    __shared__ unsigned long long rsh[256];
    float* csh = raw + 16;
    const int tid = threadIdx.x;
    const int tile0 = blockIdx.x * TILE;
    const int f = blockIdx.y, b = blockIdx.z;
    const float* tb = target + b * NN;
    const float* rb = recon + b * NN + f * 256;

    for (int j = tid; j < 512; j += 256) wsh[j] = hamm(j) * rb[j];
    for (int i = tid; i < 4624; i += 256) {
        int gi = tile0 - 528 + i;
        raw[i] = (gi >= 0 && gi < NN) ? tb[gi] : 0.0f;
    }
    __syncthreads();

    float acc[16];
#pragma unroll
    for (int t = 0; t < 16; t++) acc[t] = 0.0f;
    conv16(csh, wsh, tid, acc);

    unsigned kb = (unsigned)(tile0 + 16 * tid);
    unsigned long long key = packkey(acc[0], kb);
#pragma unroll
    for (int t = 1; t < 16; t++) {
        unsigned long long kt = packkey(acc[t], kb + t);
        if (kt > key) key = kt;
    }
    rsh[tid] = key;
    __syncthreads();
    for (int s = 128; s > 0; s >>= 1) {
        if (tid < s) { if (rsh[tid + s] > rsh[tid]) rsh[tid] = rsh[tid + s]; }
        __syncthreads();
    }
    if (tid == 0) atomicMax(&d_amax[b * FF + f], rsh[0]);
}

// ---- per-frame params + moments for the far-field expansion ----
__global__ void k_prep(const float* __restrict__ recon) {
    __shared__ float4 red[128];
    const int bf = blockIdx.x;
    const int b = bf / FF, f = bf % FF;
    const int tid = threadIdx.x;
    const unsigned a = 0xFFFFFFFFu - (unsigned)(d_amax[bf] & 0xFFFFFFFFull);
    const bool delta = (a == 0u);
    const float r = (float)a * (1.0f / 32769.0f);
    const float beta = delta ? 1.0f
        : ((a & 1u) ? -1.0f : 1.0f) * sinpif(r) * (1.0f / 65536.0f);
    const float* rb = recon + b * NN + f * 256;

    float m0 = 0.f, m1 = 0.f, m2 = 0.f, m3 = 0.f;
#pragma unroll
    for (int q = 0; q < 4; q++) {
        int j = tid * 4 + q;
        float s = (j & 1) ? -1.0f : 1.0f;
        float g = beta * s * hamm(j) * rb[j];
        float tau = (255.5f - (float)j) * (1.0f / 256.0f);
        float t2 = tau * tau;
        m0 += g; m1 += g * tau; m2 += g * t2; m3 += g * t2 * tau;
    }
    red[tid] = make_float4(m0, m1, m2, m3);
    __syncthreads();
    for (int s = 64; s > 0; s >>= 1) {
        if (tid < s) {
            float4 x = red[tid], y = red[tid + s];
            red[tid] = make_float4(x.x+y.x, x.y+y.y, x.z+y.z, x.w+y.w);
        }
        __syncthreads();
    }
    if (tid == 0) {
        float* e = d_ftab + bf * 8;
        float4 m = red[0];
        e[0] = __int_as_float((int)a);
        e[1] = r;
        e[2] = m.x; e[3] = m.y; e[4] = m.z; e[5] = m.w;
    }
}

// ---- far-field: cubic cot-Taylor x moments; frame-chunked for occupancy ----
__global__ __launch_bounds__(256) void k_far() {
    __shared__ float ft[FCH * 8];
    const int tid = threadIdx.x;
    const int chunk = blockIdx.y, b = blockIdx.z;
    const int f0 = chunk * FCH;
    const int nf = (f0 + FCH < FF) ? FCH : (FF - f0);
    for (int i = tid; i < nf * 8; i += 256) ft[i] = d_ftab[(b * FF + f0) * 8 + i];
    __syncthreads();

    const int m0i = blockIdx.x * 1024 + tid * 4;
    float F[4] = {0.f, 0.f, 0.f, 0.f};
    const float G = 0.01227184630f;   // pi/256

    for (int f = 0; f < nf; f++) {
        const float* e = ft + f * 8;
        int a = __float_as_int(e[0]);
        if (a == 0) continue;                      // delta frame: fully in near band
        float r = e[1], M0 = e[2], M1 = e[3], M2 = e[4], M3 = e[5];
        float dbase = (float)(m0i - a) + (r - 255.5f);
        int rel = m0i - (a - NEAR_LO);
#pragma unroll
        for (int k = 0; k < 4; k++) {
            if ((unsigned)(rel + k) < (unsigned)NEAR_SPAN) continue;  // near band: exact
            float u = (dbase + (float)k) * (1.0f / 65536.0f);
            float c0 = __fdividef(cospif(u), sinpif(u));
            float c2 = c0 * c0;
            float q = c2 + 1.0f;
            float t = fmaf(G, fmaf(G, (c2 + 0.33333333f) * M3, -c0 * M2), M1);
            F[k] = fmaf(c0, M0, fmaf(-G * q, t, F[k]));
        }
    }
    // P = (-1)^m * F ; m0i multiple of 4 -> signs + - + -
    float4 outv = make_float4(F[0], -F[1], F[2], -F[3]);
    *(float4*)(d_Pc + ((size_t)(chunk * BB + b)) * NN + m0i) = outv;
}

// ---- near-field: exact 512-tap conv on the 4096-wide band around the pole ----
__global__ __launch_bounds__(256, 2) void k_near(const float* __restrict__ recon) {
    __shared__ __align__(16) float raw[4640];
    __shared__ __align__(16) float wsh[512];
    float* csh = raw + 16;
    const int tid = threadIdx.x;
    const int f = blockIdx.y, b = blockIdx.z;
    const int bf = b * FF + f;
    const unsigned a = 0xFFFFFFFFu - (unsigned)(d_amax[bf] & 0xFFFFFFFFull);
    const int tile0 = (int)a - NEAR_LO;
    const bool delta = (a == 0u);
    const float r = (float)a * (1.0f / 32769.0f);
    const float beta = delta ? 1.0f
        : ((a & 1u) ? -1.0f : 1.0f) * sinpif(r) * (1.0f / 65536.0f);
    const float* rb = recon + b * NN + f * 256;

    for (int j = tid; j < 512; j += 256) {
        float s = (j & 1) ? -1.0f : 1.0f;
        wsh[j] = beta * s * hamm(j) * rb[j];
    }
    for (int i = tid; i < 4624; i += 256) {
        int d = tile0 - 528 + i;
        float v;
        if (delta) {
            v = (d == 0) ? 1.0f : 0.0f;
        } else if (d < -511) {
            v = 0.0f;
        } else {
            float u = ((float)(d - (int)a) + r) * (1.0f / 65536.0f);
            v = __fdividef(cospif(u), sinpif(u));
        }
        raw[i] = v;
    }
    __syncthreads();

    float acc[16];
#pragma unroll
    for (int t = 0; t < 16; t++) acc[t] = 0.0f;
    conv16(csh, wsh, tid, acc);

    const int mb = tile0 + 16 * tid;
    float* Pb = d_Pc + b * NN;        // chunk 0 partial
#pragma unroll
    for (int t = 0; t < 16; t++) {
        int m = mb + t;
        if ((unsigned)m < (unsigned)NN) {
            float val = (m & 1) ? -acc[t] : acc[t];
            atomicAdd(Pb + m, val);
        }
    }
}

// ---- parallel MSE reduction ----
__global__ void k_loss(const float* __restrict__ target) {
    __shared__ double red[256];
    const int tid = threadIdx.x;
    double s = 0.0;
    for (int i = blockIdx.x * 256 + tid; i < BB * NN; i += gridDim.x * 256) {
        int b = i >> 15, m = i & (NN - 1);
        float p = 0.f;
#pragma unroll
        for (int c = 0; c < NCH; c++)
            p += d_Pc[((size_t)(c * BB + b)) * NN + m];
        double dd = (double)p - (double)target[i];
        s += dd * dd;
    }
    red[tid] = s;
    __syncthreads();
    for (int st = 128; st > 0; st >>= 1) {
        if (tid < st) red[tid] += red[tid + st];
        __syncthreads();
    }
    if (tid == 0) atomicAdd(&d_acc, red[0]);
}

__global__ void k_final(float* __restrict__ out) {
    out[0] = (float)(d_acc / (double)(BB * NN));
}

extern "C" void kernel_launch(void* const* d_in, const int* in_sizes, int n_in,
                              void* d_out, int out_size) {
    const float* recon  = (const float*)d_in[0];
    const float* target = (const float*)d_in[1];
    float* out = (float*)d_out;
    (void)in_sizes; (void)n_in; (void)out_size;

    k_init<<<2, 256>>>();
    k_conv1<<<dim3(NN / TILE, FF, BB), 256>>>(recon, target);
    k_prep<<<NFT, 128>>>(recon);
    k_far<<<dim3(NN / 1024, NCH, BB), 256>>>();
    k_near<<<dim3(1, FF, BB), 256>>>(recon);
    k_loss<<<128, 256>>>(target);
    k_final<<<1, 1>>>(out);
}

// round 9
// speedup vs baseline: 1.2379x; 1.1368x over previous
#include <cuda_runtime.h>
#include <cuda_bf16.h>

#define NN 32768
#define BB 4
#define WW 512
#define FF 127
#define NFT (BB*FF)
#define TILE 4096
#define NEAR_LO 1792
#define NEAR_SPAN 4096
#define FCH 16            // frames per far-chunk
#define NCH 8             // far chunks

// ---- device scratch ----
__device__ unsigned long long d_amax[NFT];
__device__ float d_Pc[NCH * BB * NN];      // far partials; near adds into chunk 0
__device__ float d_ftab[NFT * 8];          // per frame: {a_bits, r, M0, M1, M2, M3, -, -}
__device__ double d_acc;

__device__ __forceinline__ float hamm(int j) {
    return 0.54f - 0.46f * cospif((float)j * (1.0f / 256.0f));
}

// order-preserving pack; ties -> smaller k wins (matches jnp.argmax)
__device__ __forceinline__ unsigned long long packkey(float v, unsigned k) {
    unsigned u = __float_as_uint(v);
    u = (u & 0x80000000u) ? ~u : (u | 0x80000000u);
    return ((unsigned long long)u << 32) | (0xFFFFFFFFu - k);
}

__global__ void k_init() {
    int i = blockIdx.x * blockDim.x + threadIdx.x;
    if (i < NFT) d_amax[i] = 0ull;
    if (i == NFT) d_acc = 0.0;
}

// Register-sliding-window 512-tap conv: 16 outputs/thread, 8 taps/iter.
// csh[i] = x[tile0 - 512 + i]; csh valid for i in [-16, 16*nthr + 512).
// (Empirically best structure: R5 = 391us; FFMA2/circular/full-unroll/reload
//  variants all regressed.)
__device__ __forceinline__ void conv16(const float* __restrict__ csh,
                                       const float* __restrict__ wsh,
                                       int tid, float* __restrict__ acc) {
    float X[24];   // X[i] = csh[16*tid + 504 - j0 + i]
    const float* base = csh + 16 * tid + 504;
#pragma unroll
    for (int i = 0; i < 6; i++) {
        float4 v = *(const float4*)(base + 4 * i);
        X[4*i+0]=v.x; X[4*i+1]=v.y; X[4*i+2]=v.z; X[4*i+3]=v.w;
    }
#pragma unroll 8
    for (int j0 = 0; j0 < 512; j0 += 8) {
        float4 w0 = *(const float4*)(wsh + j0);
        float4 w1 = *(const float4*)(wsh + j0 + 4);
        float wr[8] = {w0.x,w0.y,w0.z,w0.w,w1.x,w1.y,w1.z,w1.w};
#pragma unroll
        for (int c = 0; c < 8; c++)
#pragma unroll
            for (int t = 0; t < 16; t++)
                acc[t] = fmaf(wr[c], X[8 + t - c], acc[t]);
        // slide window by 8: new X[i] = old X[i-8] for i>=8; X[0..7] fresh
#pragma unroll
        for (int i = 23; i >= 8; i--) X[i] = X[i - 8];
        float4 n0 = *(const float4*)(base - j0 - 8);
        float4 n1 = *(const float4*)(base - j0 - 4);
        X[0]=n0.x; X[1]=n0.y; X[2]=n0.z; X[3]=n0.w;
        X[4]=n1.x; X[5]=n1.y; X[6]=n1.z; X[7]=n1.w;
    }
}

// ---- conv1: fm[b,f,k] = sum_j w[j]*t[k-j]; block argmax -> atomicMax ----
__global__ __launch_bounds__(256, 2) void k_conv1(const float* __restrict__ recon,
                                                  const float* __restrict__ target) {
    __shared__ __align__(16) float raw[4640];
    __shared__ __align__(16) float wsh[512];
    __shared__ unsigned long long rsh[256];
    float* csh = raw + 16;
    const int tid = threadIdx.x;
    const int tile0 = blockIdx.x * TILE;
    const int f = blockIdx.y, b = blockIdx.z;
    const float* tb = target + b * NN;
    const float* rb = recon + b * NN + f * 256;

    for (int j = tid; j < 512; j += 256) wsh[j] = hamm(j) * rb[j];
    for (int i = tid; i < 4624; i += 256) {
        int gi = tile0 - 528 + i;
        raw[i] = (gi >= 0 && gi < NN) ? tb[gi] : 0.0f;
    }
    __syncthreads();

    float acc[16];
#pragma unroll
    for (int t = 0; t < 16; t++) acc[t] = 0.0f;
    conv16(csh, wsh, tid, acc);

    unsigned kb = (unsigned)(tile0 + 16 * tid);
    unsigned long long key = packkey(acc[0], kb);
#pragma unroll
    for (int t = 1; t < 16; t++) {
        unsigned long long kt = packkey(acc[t], kb + t);
        if (kt > key) key = kt;
    }
    rsh[tid] = key;
    __syncthreads();
    for (int s = 128; s > 0; s >>= 1) {
        if (tid < s) { if (rsh[tid + s] > rsh[tid]) rsh[tid] = rsh[tid + s]; }
        __syncthreads();
    }
    if (tid == 0) atomicMax(&d_amax[b * FF + f], rsh[0]);
}

// ---- per-frame params + moments for the far-field expansion ----
__global__ void k_prep(const float* __restrict__ recon) {
    __shared__ float4 red[128];
    const int bf = blockIdx.x;
    const int b = bf / FF, f = bf % FF;
    const int tid = threadIdx.x;
    const unsigned a = 0xFFFFFFFFu - (unsigned)(d_amax[bf] & 0xFFFFFFFFull);
    const bool delta = (a == 0u);
    const float r = (float)a * (1.0f / 32769.0f);
    const float beta = delta ? 1.0f
        : ((a & 1u) ? -1.0f : 1.0f) * sinpif(r) * (1.0f / 65536.0f);
    const float* rb = recon + b * NN + f * 256;

    float m0 = 0.f, m1 = 0.f, m2 = 0.f, m3 = 0.f;
#pragma unroll
    for (int q = 0; q < 4; q++) {
        int j = tid * 4 + q;
        float s = (j & 1) ? -1.0f : 1.0f;
        float g = beta * s * hamm(j) * rb[j];
        float tau = (255.5f - (float)j) * (1.0f / 256.0f);
        float t2 = tau * tau;
        m0 += g; m1 += g * tau; m2 += g * t2; m3 += g * t2 * tau;
    }
    red[tid] = make_float4(m0, m1, m2, m3);
    __syncthreads();
    for (int s = 64; s > 0; s >>= 1) {
        if (tid < s) {
            float4 x = red[tid], y = red[tid + s];
            red[tid] = make_float4(x.x+y.x, x.y+y.y, x.z+y.z, x.w+y.w);
        }
        __syncthreads();
    }
    if (tid == 0) {
        float* e = d_ftab + bf * 8;
        float4 m = red[0];
        e[0] = __int_as_float((int)a);
        e[1] = r;
        e[2] = m.x; e[3] = m.y; e[4] = m.z; e[5] = m.w;
    }
}

// ---- far-field: cubic cot-Taylor x moments; frame-chunked for occupancy ----
__global__ __launch_bounds__(256) void k_far() {
    __shared__ float ft[FCH * 8];
    const int tid = threadIdx.x;
    const int chunk = blockIdx.y, b = blockIdx.z;
    const int f0 = chunk * FCH;
    const int nf = (f0 + FCH < FF) ? FCH : (FF - f0);
    for (int i = tid; i < nf * 8; i += 256) ft[i] = d_ftab[(b * FF + f0) * 8 + i];
    __syncthreads();

    const int m0i = blockIdx.x * 1024 + tid * 4;
    float F[4] = {0.f, 0.f, 0.f, 0.f};
    const float G = 0.01227184630f;   // pi/256

    for (int f = 0; f < nf; f++) {
        const float* e = ft + f * 8;
        int a = __float_as_int(e[0]);
        if (a == 0) continue;                      // delta frame: fully in near band
        float r = e[1], M0 = e[2], M1 = e[3], M2 = e[4], M3 = e[5];
        float dbase = (float)(m0i - a) + (r - 255.5f);
        int rel = m0i - (a - NEAR_LO);
#pragma unroll
        for (int k = 0; k < 4; k++) {
            if ((unsigned)(rel + k) < (unsigned)NEAR_SPAN) continue;  // near band: exact
            float u = (dbase + (float)k) * (1.0f / 65536.0f);
            float c0 = __fdividef(cospif(u), sinpif(u));
            float c2 = c0 * c0;
            float q = c2 + 1.0f;
            float t = fmaf(G, fmaf(G, (c2 + 0.33333333f) * M3, -c0 * M2), M1);
            F[k] = fmaf(c0, M0, fmaf(-G * q, t, F[k]));
        }
    }
    // P = (-1)^m * F ; m0i multiple of 4 -> signs + - + -
    float4 outv = make_float4(F[0], -F[1], F[2], -F[3]);
    *(float4*)(d_Pc + ((size_t)(chunk * BB + b)) * NN + m0i) = outv;
}

// ---- near-field: exact 512-tap conv, 2 blocks x 2048 outputs per frame ----
__global__ __launch_bounds__(128, 4) void k_near(const float* __restrict__ recon) {
    __shared__ __align__(16) float raw[2592];   // csh = raw+8
    __shared__ __align__(16) float wsh[512];
    float* csh = raw + 8;
    const int tid = threadIdx.x;
    const int f = blockIdx.y, b = blockIdx.z;
    const int bf = b * FF + f;
    const unsigned a = 0xFFFFFFFFu - (unsigned)(d_amax[bf] & 0xFFFFFFFFull);
    const int tile0 = (int)a - NEAR_LO + blockIdx.x * 2048;
    if (tile0 >= NN || tile0 + 2048 <= 0) return;
    const bool delta = (a == 0u);
    const float r = (float)a * (1.0f / 32769.0f);
    const float beta = delta ? 1.0f
        : ((a & 1u) ? -1.0f : 1.0f) * sinpif(r) * (1.0f / 65536.0f);
    const float* rb = recon + b * NN + f * 256;

    for (int j = tid; j < 512; j += 128) {
        float s = (j & 1) ? -1.0f : 1.0f;
        wsh[j] = beta * s * hamm(j) * rb[j];
    }
    for (int i = tid; i < 2592; i += 128) {
        int d = tile0 - 520 + i;
        float v;
        if (delta) {
            v = (d == 0) ? 1.0f : 0.0f;
        } else if (d < -511) {
            v = 0.0f;
        } else {
            float u = ((float)(d - (int)a) + r) * (1.0f / 65536.0f);
            v = __fdividef(cospif(u), sinpif(u));
        }
        raw[i] = v;
    }
    __syncthreads();

    float acc[16];
#pragma unroll
    for (int t = 0; t < 16; t++) acc[t] = 0.0f;
    conv16(csh, wsh, tid, acc);

    const int mb = tile0 + 16 * tid;
    float* Pb = d_Pc + b * NN;        // chunk 0 partial
#pragma unroll
    for (int t = 0; t < 16; t++) {
        int m = mb + t;
        if ((unsigned)m < (unsigned)NN) {
            float val = (m & 1) ? -acc[t] : acc[t];
            atomicAdd(Pb + m, val);
        }
    }
}

// ---- parallel MSE reduction ----
__global__ void k_loss(const float* __restrict__ target) {
    __shared__ double red[256];
    const int tid = threadIdx.x;
    double s = 0.0;
    for (int i = blockIdx.x * 256 + tid; i < BB * NN; i += gridDim.x * 256) {
        int b = i >> 15, m = i & (NN - 1);
        float p = 0.f;
#pragma unroll
        for (int c = 0; c < NCH; c++)
            p += d_Pc[((size_t)(c * BB + b)) * NN + m];
        double dd = (double)p - (double)target[i];
        s += dd * dd;
    }
    red[tid] = s;
    __syncthreads();
    for (int st = 128; st > 0; st >>= 1) {
        if (tid < st) red[tid] += red[tid + st];
        __syncthreads();
    }
    if (tid == 0) atomicAdd(&d_acc, red[0]);
}

__global__ void k_final(float* __restrict__ out) {
    out[0] = (float)(d_acc / (double)(BB * NN));
}

extern "C" void kernel_launch(void* const* d_in, const int* in_sizes, int n_in,
                              void* d_out, int out_size) {
    const float* recon  = (const float*)d_in[0];
    const float* target = (const float*)d_in[1];
    float* out = (float*)d_out;
    (void)in_sizes; (void)n_in; (void)out_size;

    k_init<<<2, 256>>>();
    k_conv1<<<dim3(NN / TILE, FF, BB), 256>>>(recon, target);
    k_prep<<<NFT, 128>>>(recon);
    k_far<<<dim3(NN / 1024, NCH, BB), 256>>>();
    k_near<<<dim3(2, FF, BB), 128>>>(recon);
    k_loss<<<128, 256>>>(target);
    k_final<<<1, 1>>>(out);
}